// round 8
// baseline (speedup 1.0000x reference)
#include <cuda_runtime.h>
#include <cstdint>
#include <math.h>

// GAT layer, v6b (v6 + adjS init fix; mma.sync — tcgen05 unavailable on sm_103 target):
//   Dense row packing: 16 batches x 12 nodes = 192 rows = 12 exact m16 tiles.
//   384 threads / 12 warps; warp = 32 rows x 64 cols.
//   W fragments precomputed (tf32) once; X staged as raw fp32 bits (tf32 HW
//   truncation). Chunk staging double-buffered with cp.async groups.
//   Epilogue: H -> smem, masked softmax, alpha@H, elu (coalesced, shuffle-free).

#define B_TOT   32768
#define N_NODE  12
#define F_IN    256
#define D_OUT   128
#define BPC     16
#define THREADS 384
#define KC      64
#define BLK     132            // words per fragment-block (128 used + 4 pad)
#define HST     132            // Hs row stride (words)

#define WBUF_WORDS (64 * BLK)               // 8448  (8 ks x 8 tp blocks)
#define XBUF_WORDS (96 * BLK)               // 12672 (12 rowgroups x 8 ks blocks)
#define CH_WORDS   (WBUF_WORDS + XBUF_WORDS) // 21120 per chunk buffer
#define SMEM_WORDS (2 * CH_WORDS + 256 + 144 + BPC * 144)

__device__ uint32_t WtF_g[4 * 64 * 32 * 4];   // [chunk][blk][lane][v] tf32 bits

__device__ __forceinline__ uint32_t f2tf32(float f) {
    uint32_t r;
    asm("cvt.rna.tf32.f32 %0, %1;" : "=r"(r) : "f"(f));
    return r;
}

__device__ __forceinline__ void mma_tf32(float& c0, float& c1, float& c2, float& c3,
                                         uint32_t a0, uint32_t a1, uint32_t a2, uint32_t a3,
                                         uint32_t b0, uint32_t b1) {
    asm("mma.sync.aligned.m16n8k8.row.col.f32.tf32.tf32.f32 "
        "{%0,%1,%2,%3},{%4,%5,%6,%7},{%8,%9},{%0,%1,%2,%3};"
        : "+f"(c0), "+f"(c1), "+f"(c2), "+f"(c3)
        : "r"(a0), "r"(a1), "r"(a2), "r"(a3), "r"(b0), "r"(b1));
}

__device__ __forceinline__ uint32_t smem_u32(const void* p) {
    uint32_t a;
    asm("{ .reg .u64 t; cvta.to.shared.u64 t, %1; cvt.u32.u64 %0, t; }" : "=r"(a) : "l"(p));
    return a;
}

__device__ __forceinline__ void cp16(uint32_t dst, const void* src) {
    asm volatile("cp.async.ca.shared.global [%0], [%1], 16;" :: "r"(dst), "l"(src));
}
__device__ __forceinline__ void cp4(uint32_t dst, const void* src) {
    asm volatile("cp.async.ca.shared.global [%0], [%1], 4;" :: "r"(dst), "l"(src));
}
__device__ __forceinline__ void cp_commit() {
    asm volatile("cp.async.commit_group;");
}
__device__ __forceinline__ void cp_wait1() {
    asm volatile("cp.async.wait_group 1;" ::: "memory");
}
__device__ __forceinline__ void cp_wait0() {
    asm volatile("cp.async.wait_group 0;" ::: "memory");
}

__device__ __forceinline__ float elu_f(float v) {
    return v > 0.f ? v : expm1f(v);
}

// ---- pre-kernel: fragment-ordered tf32 W ----------------------------------
// word (ch, blk=(ks,tp), lane=(qq,mm), v=(tl,hi)) = tf32(W[k][n]),
//   k = 64ch + 8ks + mm + 4hi,  n = 16tp + 8tl + qq
__global__ void wfrag_pre_kernel(const float* __restrict__ W) {
    int idx = blockIdx.x * 256 + threadIdx.x;      // 0..32767
    int v   = idx & 3;
    int l   = (idx >> 2) & 31;
    int blk = (idx >> 7) & 63;
    int ch  = idx >> 13;
    int qq = l >> 2, mm = l & 3;
    int tl = v >> 1, hi = v & 1;
    int ks = blk >> 3, tp = blk & 7;
    int k = ch * 64 + ks * 8 + mm + 4 * hi;
    int n = 16 * tp + 8 * tl + qq;
    WtF_g[idx] = f2tf32(W[k * D_OUT + n]);
}

// stage chunk c into buffer (base word offset bw)
__device__ __forceinline__ void stage_chunk(uint32_t sb, uint32_t bw, int c,
                                            const float* __restrict__ xbase, int tid) {
    // W: 2048 float4, pure 16B copies, conflict-free
    const uint32_t* wsrc = WtF_g + c * 8192;
    #pragma unroll
    for (int idx = tid; idx < 2048; idx += THREADS) {
        int blk = idx >> 5, l = idx & 31;
        cp16(sb + (bw + blk * BLK + l * 4) * 4, wsrc + idx * 4);
    }
    // X: 192 dense rows x 16 float4, raw fp32 bits -> fragment slots (4B copies)
    #pragma unroll
    for (int idx = tid; idx < 3072; idx += THREADS) {
        int row = idx >> 4;
        int c4  = idx & 15;
        const float* src = xbase + (size_t)row * F_IN + c * KC + 4 * c4;
        int g = row >> 4, qq = row & 7, rbit = (row >> 3) & 1;
        int ks = c4 >> 1, hi = c4 & 1;
        uint32_t dst = sb + (bw + WBUF_WORDS + (g * 8 + ks) * BLK
                             + qq * 16 + 2 * hi + rbit) * 4;
        #pragma unroll
        for (int s = 0; s < 4; s++) cp4(dst + s * 16, src + s);
    }
    cp_commit();
}

__global__ void __launch_bounds__(THREADS, 1)
gat_fused_kernel(const float* __restrict__ x,    // [B, N, F]
                 const float* __restrict__ adj,  // [N, N]
                 const float* __restrict__ a,    // [2D, 1]
                 float* __restrict__ out)        // [B, N, D]
{
    extern __shared__ uint32_t smem[];
    float*    Hs     = (float*)smem;                  // aliases buffers post-GEMM
    float*    sA     = (float*)(smem + 2 * CH_WORDS);
    float*    adjS   = sA + 2 * D_OUT;
    float*    alphaS = adjS + N_NODE * N_NODE;        // [16][144]

    const uint32_t sb = smem_u32(smem);

    const int tid  = threadIdx.x;
    const int w    = tid >> 5;
    const int lane = tid & 31;
    const int p    = w >> 1;          // row-pair: rows 32p..32p+31
    const int h    = w & 1;           // D half

    if (tid < 256) sA[tid] = a[tid];
    if (tid < N_NODE * N_NODE) adjS[tid] = adj[tid];   // FIX: full 144 entries

    const float* xbase = x + (size_t)blockIdx.x * (BPC * N_NODE) * F_IN;

    float acc[2][8][4];
    #pragma unroll
    for (int tb = 0; tb < 2; tb++)
        #pragma unroll
        for (int t = 0; t < 8; t++)
            acc[tb][t][0] = acc[tb][t][1] = acc[tb][t][2] = acc[tb][t][3] = 0.f;

    // prologue: prefetch chunks 0 and 1
    stage_chunk(sb, 0, 0, xbase, tid);
    stage_chunk(sb, CH_WORDS, 1, xbase, tid);

    #pragma unroll
    for (int c = 0; c < 4; c++) {
        const uint32_t bw = (c & 1) ? CH_WORDS : 0u;
        if (c < 3) cp_wait1(); else cp_wait0();
        __syncthreads();

        const uint32_t* Wp = smem + bw + lane * 4;
        const uint32_t* Xp = smem + bw + WBUF_WORDS + lane * 4;
        #pragma unroll
        for (int ks = 0; ks < 8; ks++) {
            uint4 Af0 = *(const uint4*)(Xp + ((2 * p)     * 8 + ks) * BLK);
            uint4 Af1 = *(const uint4*)(Xp + ((2 * p + 1) * 8 + ks) * BLK);
            #pragma unroll
            for (int tp = 0; tp < 4; tp++) {
                uint4 Bf = *(const uint4*)(Wp + (ks * 8 + 4 * h + tp) * BLK);
                mma_tf32(acc[0][2*tp][0],   acc[0][2*tp][1],   acc[0][2*tp][2],   acc[0][2*tp][3],
                         Af0.x, Af0.y, Af0.z, Af0.w, Bf.x, Bf.y);
                mma_tf32(acc[0][2*tp+1][0], acc[0][2*tp+1][1], acc[0][2*tp+1][2], acc[0][2*tp+1][3],
                         Af0.x, Af0.y, Af0.z, Af0.w, Bf.z, Bf.w);
                mma_tf32(acc[1][2*tp][0],   acc[1][2*tp][1],   acc[1][2*tp][2],   acc[1][2*tp][3],
                         Af1.x, Af1.y, Af1.z, Af1.w, Bf.x, Bf.y);
                mma_tf32(acc[1][2*tp+1][0], acc[1][2*tp+1][1], acc[1][2*tp+1][2], acc[1][2*tp+1][3],
                         Af1.x, Af1.y, Af1.z, Af1.w, Bf.z, Bf.w);
            }
        }
        __syncthreads();
        if (c < 2) stage_chunk(sb, bw, c + 2, xbase, tid);
    }

    // ---- spill H (192 dense rows x 128) into Hs ----------------------------
    const int q = lane >> 2;
    const int m = lane & 3;
    #pragma unroll
    for (int tb = 0; tb < 2; tb++) {
        const int row0 = 32 * p + 16 * tb + q;
        #pragma unroll
        for (int tp = 0; tp < 4; tp++) {
            #pragma unroll
            for (int tl = 0; tl < 2; tl++) {
                int ai  = 2 * tp + tl;
                int col = 64 * h + 16 * tp + 8 * tl + 2 * m;
                float* r0p = Hs + row0 * HST + col;
                *(float2*)r0p = make_float2(acc[tb][ai][0], acc[tb][ai][1]);
                *(float2*)(r0p + 8 * HST) = make_float2(acc[tb][ai][2], acc[tb][ai][3]);
            }
        }
    }
    __syncthreads();

    // ---- attention per batch (warps loop over batches w, w+12) -------------
    for (int bb = w; bb < BPC; bb += 12) {
        float sj = 0.f, si = 0.f;
        if (lane < N_NODE) {
            const float4* hr  = (const float4*)(Hs + (bb * N_NODE + lane) * HST);
            const float4* ajp = (const float4*)sA;
            const float4* aip = (const float4*)(sA + D_OUT);
            #pragma unroll
            for (int cc = 0; cc < 32; cc++) {
                float4 hv = hr[cc];
                float4 av = ajp[cc], bv = aip[cc];
                sj += hv.x*av.x + hv.y*av.y + hv.z*av.z + hv.w*av.w;
                si += hv.x*bv.x + hv.y*bv.y + hv.z*bv.z + hv.w*bv.w;
            }
        }
        float sjv[N_NODE];
        #pragma unroll
        for (int j = 0; j < N_NODE; j++)
            sjv[j] = __shfl_sync(0xffffffffu, sj, j);

        if (lane < N_NODE) {
            float ev[N_NODE];
            float mx = -INFINITY;
            #pragma unroll
            for (int j = 0; j < N_NODE; j++) {
                float e = si + sjv[j];
                e = e > 0.f ? e : 0.2f * e;
                ev[j] = (adjS[lane * N_NODE + j] == 1.0f) ? e : -INFINITY;
                mx = fmaxf(mx, ev[j]);
            }
            float sum = 0.f;
            #pragma unroll
            for (int j = 0; j < N_NODE; j++) { ev[j] = __expf(ev[j] - mx); sum += ev[j]; }
            float inv = 1.f / sum;
            #pragma unroll
            for (int j = 0; j < N_NODE; j++)
                alphaS[bb * 144 + lane * N_NODE + j] = ev[j] * inv;
        }
        __syncwarp();

        // h' = alpha @ H, elu, store
        float4 o[N_NODE];
        #pragma unroll
        for (int i = 0; i < N_NODE; i++) o[i] = make_float4(0.f, 0.f, 0.f, 0.f);

        const float* hb  = Hs + bb * N_NODE * HST + lane * 4;
        const float* alw = alphaS + bb * 144;
        #pragma unroll
        for (int j = 0; j < N_NODE; j++) {
            float4 hv = *(const float4*)(hb + j * HST);
            #pragma unroll
            for (int i = 0; i < N_NODE; i++) {
                float al = alw[i * N_NODE + j];
                o[i].x += al * hv.x;
                o[i].y += al * hv.y;
                o[i].z += al * hv.z;
                o[i].w += al * hv.w;
            }
        }
        float* ob = out + ((size_t)blockIdx.x * (BPC * N_NODE) + bb * N_NODE) * D_OUT
                  + lane * 4;
        #pragma unroll
        for (int i = 0; i < N_NODE; i++) {
            float4 r;
            r.x = elu_f(o[i].x);
            r.y = elu_f(o[i].y);
            r.z = elu_f(o[i].z);
            r.w = elu_f(o[i].w);
            *(float4*)(ob + (size_t)i * D_OUT) = r;
        }
    }
}

extern "C" void kernel_launch(void* const* d_in, const int* in_sizes, int n_in,
                              void* d_out, int out_size) {
    const float* x   = (const float*)d_in[0];   // [32768,12,256]
    const float* adj = (const float*)d_in[1];   // [12,12]
    const float* W   = (const float*)d_in[2];   // [256,128]
    const float* a   = (const float*)d_in[3];   // [256,1]
    float* out       = (float*)d_out;           // [32768,12,128]

    wfrag_pre_kernel<<<128, 256>>>(W);

    const int smem_bytes = SMEM_WORDS * 4;
    cudaFuncSetAttribute(gat_fused_kernel,
                         cudaFuncAttributeMaxDynamicSharedMemorySize, smem_bytes);

    gat_fused_kernel<<<B_TOT / BPC, THREADS, smem_bytes>>>(x, adj, a, out);
}

// round 9
// speedup vs baseline: 1.2023x; 1.2023x over previous
#include <cuda_runtime.h>
#include <cstdint>
#include <math.h>

// GAT layer, v7 (mma.sync; tcgen05 unavailable on this build's sm_103 target):
//   v5 tiling (256 thr, 8 warps, warp = batch-pair x D-half 32x64, 2 CTAs/SM) with:
//   - B (W) fragments read DIRECTLY from L2-hot global WtF_g (coalesced LDG.128);
//     no W staging, no B smem traffic.
//   - X staging double-buffered with cp.async groups (latency overlapped).
//   - H -> smem spill + coalesced attention epilogue (unchanged).

#define B_TOT   32768
#define N_NODE  12
#define F_IN    256
#define D_OUT   128
#define BPC     8
#define KC      64
#define BLK     132            // words per X fragment-block (128 used + 4 pad)
#define HST     132            // Hs row stride (words)

#define XBUF_WORDS (64 * BLK)              // 8448 per buffer (8 batches x 8 ks blocks)
#define HS_WORDS   (2 * XBUF_WORDS)        // 16896 = 128 rows * 132 (exact alias fit)

__device__ uint32_t WtF_g[4 * 64 * 32 * 4];   // [chunk][blk][lane][v] tf32 bits

__device__ __forceinline__ uint32_t f2tf32(float f) {
    uint32_t r;
    asm("cvt.rna.tf32.f32 %0, %1;" : "=r"(r) : "f"(f));
    return r;
}

__device__ __forceinline__ void mma_tf32(float& c0, float& c1, float& c2, float& c3,
                                         uint32_t a0, uint32_t a1, uint32_t a2, uint32_t a3,
                                         uint32_t b0, uint32_t b1) {
    asm("mma.sync.aligned.m16n8k8.row.col.f32.tf32.tf32.f32 "
        "{%0,%1,%2,%3},{%4,%5,%6,%7},{%8,%9},{%0,%1,%2,%3};"
        : "+f"(c0), "+f"(c1), "+f"(c2), "+f"(c3)
        : "r"(a0), "r"(a1), "r"(a2), "r"(a3), "r"(b0), "r"(b1));
}

__device__ __forceinline__ uint32_t smem_u32(const void* p) {
    uint32_t a;
    asm("{ .reg .u64 t; cvta.to.shared.u64 t, %1; cvt.u32.u64 %0, t; }" : "=r"(a) : "l"(p));
    return a;
}

__device__ __forceinline__ void cp4(uint32_t dst, const void* src) {
    asm volatile("cp.async.ca.shared.global [%0], [%1], 4;" :: "r"(dst), "l"(src));
}
__device__ __forceinline__ void cp_commit() {
    asm volatile("cp.async.commit_group;");
}
__device__ __forceinline__ void cp_wait1() {
    asm volatile("cp.async.wait_group 1;" ::: "memory");
}
__device__ __forceinline__ void cp_wait0() {
    asm volatile("cp.async.wait_group 0;" ::: "memory");
}

__device__ __forceinline__ float elu_f(float v) {
    return v > 0.f ? v : expm1f(v);
}

// ---- pre-kernel: fragment-ordered tf32 W ----------------------------------
// word (ch, blk=(ks,tp), lane=(qq,mm), v=(tl,hi)) = tf32(W[k][n]),
//   k = 64ch + 8ks + mm + 4hi,  n = 16tp + 8tl + qq
__global__ void wfrag_pre_kernel(const float* __restrict__ W) {
    int idx = blockIdx.x * 256 + threadIdx.x;      // 0..32767
    int v   = idx & 3;
    int l   = (idx >> 2) & 31;
    int blk = (idx >> 7) & 63;
    int ch  = idx >> 13;
    int qq = l >> 2, mm = l & 3;
    int tl = v >> 1, hi = v & 1;
    int ks = blk >> 3, tp = blk & 7;
    int k = ch * 64 + ks * 8 + mm + 4 * hi;
    int n = 16 * tp + 8 * tl + qq;
    WtF_g[idx] = f2tf32(W[k * D_OUT + n]);
}

// stage X chunk c into buffer at word offset bw (warp stages its own batch)
__device__ __forceinline__ void stage_x(uint32_t sbX, uint32_t bw, int c,
                                        const float* __restrict__ xw,
                                        int w, int lane) {
    #pragma unroll
    for (int it = 0; it < 6; it++) {
        int il  = it * 32 + lane;      // 0..191 = 12 rows x 16 float4
        int row = il >> 4;
        int c4  = il & 15;
        const float* src = xw + row * F_IN + c * KC + 4 * c4;
        int ks = c4 >> 1, hi = c4 & 1;
        int qq = row & 7, rbit = row >> 3;
        uint32_t dst = sbX + (bw + (w * 8 + ks) * BLK + qq * 16 + 2 * hi + rbit) * 4;
        #pragma unroll
        for (int s = 0; s < 4; s++) cp4(dst + s * 16, src + s);
    }
    cp_commit();
}

__global__ void __launch_bounds__(256, 2)
gat_fused_kernel(const float* __restrict__ x,    // [B, N, F]
                 const float* __restrict__ adj,  // [N, N]
                 const float* __restrict__ a,    // [2D, 1]
                 float* __restrict__ out)        // [B, N, D]
{
    extern __shared__ uint32_t smem[];
    uint32_t* XsF    = smem;                      // 2 buffers of XBUF_WORDS
    float*    Hs     = (float*)smem;              // aliases both buffers post-GEMM
    float*    sA     = (float*)(smem + HS_WORDS);
    float*    adjS   = sA + 2 * D_OUT;
    float*    alphaS = adjS + N_NODE * N_NODE;    // [8][192]

    const uint32_t sbX = smem_u32(XsF);

    const int tid  = threadIdx.x;
    const int w    = tid >> 5;
    const int lane = tid & 31;
    const int p    = w >> 1;          // batch pair
    const int h    = w & 1;           // D half
    const int b    = blockIdx.x * BPC + w;

    sA[tid] = a[tid];
    if (tid < N_NODE * N_NODE) adjS[tid] = adj[tid];

    // zero both X buffers once (padding rows 12-15 of each batch stay zero)
    for (int i = tid; i < 2 * XBUF_WORDS; i += 256) smem[i] = 0u;
    __syncthreads();

    float acc[2][8][4];
    #pragma unroll
    for (int tb = 0; tb < 2; tb++)
        #pragma unroll
        for (int t = 0; t < 8; t++)
            acc[tb][t][0] = acc[tb][t][1] = acc[tb][t][2] = acc[tb][t][3] = 0.f;

    const float* xw = x + ((size_t)b * N_NODE) * F_IN;   // warp's batch

    // prologue: prefetch chunks 0 and 1
    stage_x(sbX, 0, 0, xw, w, lane);
    stage_x(sbX, XBUF_WORDS, 1, xw, w, lane);

    #pragma unroll
    for (int c = 0; c < 4; c++) {
        const uint32_t bw = (c & 1) ? XBUF_WORDS : 0u;
        if (c < 3) cp_wait1(); else cp_wait0();
        __syncthreads();

        const uint32_t* Xw0 = XsF + bw + (2 * p)     * 8 * BLK + lane * 4;
        const uint32_t* Xw1 = XsF + bw + (2 * p + 1) * 8 * BLK + lane * 4;
        // B source: L2-hot global, coalesced 512B per warp fragment
        const uint4* __restrict__ Wg =
            (const uint4*)WtF_g + (size_t)(c * 64 + 4 * h) * 32 + lane;

        #pragma unroll
        for (int ks = 0; ks < 8; ks++) {
            uint4 Bf0 = Wg[(ks * 8 + 0) * 32];
            uint4 Bf1 = Wg[(ks * 8 + 1) * 32];
            uint4 Bf2 = Wg[(ks * 8 + 2) * 32];
            uint4 Bf3 = Wg[(ks * 8 + 3) * 32];
            uint4 Af0 = *(const uint4*)(Xw0 + ks * BLK);
            uint4 Af1 = *(const uint4*)(Xw1 + ks * BLK);

            mma_tf32(acc[0][0][0], acc[0][0][1], acc[0][0][2], acc[0][0][3],
                     Af0.x, Af0.y, Af0.z, Af0.w, Bf0.x, Bf0.y);
            mma_tf32(acc[0][1][0], acc[0][1][1], acc[0][1][2], acc[0][1][3],
                     Af0.x, Af0.y, Af0.z, Af0.w, Bf0.z, Bf0.w);
            mma_tf32(acc[1][0][0], acc[1][0][1], acc[1][0][2], acc[1][0][3],
                     Af1.x, Af1.y, Af1.z, Af1.w, Bf0.x, Bf0.y);
            mma_tf32(acc[1][1][0], acc[1][1][1], acc[1][1][2], acc[1][1][3],
                     Af1.x, Af1.y, Af1.z, Af1.w, Bf0.z, Bf0.w);

            mma_tf32(acc[0][2][0], acc[0][2][1], acc[0][2][2], acc[0][2][3],
                     Af0.x, Af0.y, Af0.z, Af0.w, Bf1.x, Bf1.y);
            mma_tf32(acc[0][3][0], acc[0][3][1], acc[0][3][2], acc[0][3][3],
                     Af0.x, Af0.y, Af0.z, Af0.w, Bf1.z, Bf1.w);
            mma_tf32(acc[1][2][0], acc[1][2][1], acc[1][2][2], acc[1][2][3],
                     Af1.x, Af1.y, Af1.z, Af1.w, Bf1.x, Bf1.y);
            mma_tf32(acc[1][3][0], acc[1][3][1], acc[1][3][2], acc[1][3][3],
                     Af1.x, Af1.y, Af1.z, Af1.w, Bf1.z, Bf1.w);

            mma_tf32(acc[0][4][0], acc[0][4][1], acc[0][4][2], acc[0][4][3],
                     Af0.x, Af0.y, Af0.z, Af0.w, Bf2.x, Bf2.y);
            mma_tf32(acc[0][5][0], acc[0][5][1], acc[0][5][2], acc[0][5][3],
                     Af0.x, Af0.y, Af0.z, Af0.w, Bf2.z, Bf2.w);
            mma_tf32(acc[1][4][0], acc[1][4][1], acc[1][4][2], acc[1][4][3],
                     Af1.x, Af1.y, Af1.z, Af1.w, Bf2.x, Bf2.y);
            mma_tf32(acc[1][5][0], acc[1][5][1], acc[1][5][2], acc[1][5][3],
                     Af1.x, Af1.y, Af1.z, Af1.w, Bf2.z, Bf2.w);

            mma_tf32(acc[0][6][0], acc[0][6][1], acc[0][6][2], acc[0][6][3],
                     Af0.x, Af0.y, Af0.z, Af0.w, Bf3.x, Bf3.y);
            mma_tf32(acc[0][7][0], acc[0][7][1], acc[0][7][2], acc[0][7][3],
                     Af0.x, Af0.y, Af0.z, Af0.w, Bf3.z, Bf3.w);
            mma_tf32(acc[1][6][0], acc[1][6][1], acc[1][6][2], acc[1][6][3],
                     Af1.x, Af1.y, Af1.z, Af1.w, Bf3.x, Bf3.y);
            mma_tf32(acc[1][7][0], acc[1][7][1], acc[1][7][2], acc[1][7][3],
                     Af1.x, Af1.y, Af1.z, Af1.w, Bf3.z, Bf3.w);
        }
        __syncthreads();
        if (c < 2) stage_x(sbX, bw, c + 2, xw, w, lane);
    }

    // ---- spill H to smem (aliases X buffers) -------------------------------
    const int q = lane >> 2;
    const int m = lane & 3;
    #pragma unroll
    for (int tb = 0; tb < 2; tb++) {
        #pragma unroll
        for (int tp = 0; tp < 4; tp++) {
            #pragma unroll
            for (int tl = 0; tl < 2; tl++) {
                int ai  = 2 * tp + tl;
                int col = 64 * h + 16 * tp + 8 * tl + 2 * m;
                float* r0p = Hs + ((2 * p + tb) * 16 + q) * HST + col;
                *(float2*)r0p = make_float2(acc[tb][ai][0], acc[tb][ai][1]);
                *(float2*)(r0p + 8 * HST) = make_float2(acc[tb][ai][2], acc[tb][ai][3]);
            }
        }
    }
    __syncthreads();

    // ---- dots + masked softmax (warp w owns batch w; lane = row i) ---------
    float sj = 0.f, si = 0.f;
    if (lane < N_NODE) {
        const float4* hr  = (const float4*)(Hs + (w * 16 + lane) * HST);
        const float4* ajp = (const float4*)sA;
        const float4* aip = (const float4*)(sA + D_OUT);
        #pragma unroll
        for (int cc = 0; cc < 32; cc++) {
            float4 hv = hr[cc];
            float4 av = ajp[cc], bv = aip[cc];
            sj += hv.x*av.x + hv.y*av.y + hv.z*av.z + hv.w*av.w;
            si += hv.x*bv.x + hv.y*bv.y + hv.z*bv.z + hv.w*bv.w;
        }
    }
    float sjv[N_NODE];
    #pragma unroll
    for (int j = 0; j < N_NODE; j++)
        sjv[j] = __shfl_sync(0xffffffffu, sj, j);

    if (lane < N_NODE) {
        float ev[N_NODE];
        float mx = -INFINITY;
        #pragma unroll
        for (int j = 0; j < N_NODE; j++) {
            float e = si + sjv[j];
            e = e > 0.f ? e : 0.2f * e;
            ev[j] = (adjS[lane * N_NODE + j] == 1.0f) ? e : -INFINITY;
            mx = fmaxf(mx, ev[j]);
        }
        float sum = 0.f;
        #pragma unroll
        for (int j = 0; j < N_NODE; j++) { ev[j] = __expf(ev[j] - mx); sum += ev[j]; }
        float inv = 1.f / sum;
        #pragma unroll
        for (int j = 0; j < N_NODE; j++)
            alphaS[w * 192 + lane * N_NODE + j] = ev[j] * inv;
    }
    __syncwarp();

    // ---- h' = alpha @ H (coalesced), elu, store ---------------------------
    float4 o[N_NODE];
    #pragma unroll
    for (int i = 0; i < N_NODE; i++) o[i] = make_float4(0.f, 0.f, 0.f, 0.f);

    const float* hb  = Hs + w * 16 * HST + lane * 4;
    const float* alw = alphaS + w * 192;
    #pragma unroll
    for (int j = 0; j < N_NODE; j++) {
        float4 hv = *(const float4*)(hb + j * HST);
        #pragma unroll
        for (int i = 0; i < N_NODE; i++) {
            float al = alw[i * N_NODE + j];
            o[i].x += al * hv.x;
            o[i].y += al * hv.y;
            o[i].z += al * hv.z;
            o[i].w += al * hv.w;
        }
    }
    #pragma unroll
    for (int i = 0; i < N_NODE; i++) {
        float4 r;
        r.x = elu_f(o[i].x);
        r.y = elu_f(o[i].y);
        r.z = elu_f(o[i].z);
        r.w = elu_f(o[i].w);
        *(float4*)(out + ((size_t)b * N_NODE + i) * D_OUT + lane * 4) = r;
    }
}

extern "C" void kernel_launch(void* const* d_in, const int* in_sizes, int n_in,
                              void* d_out, int out_size) {
    const float* x   = (const float*)d_in[0];   // [32768,12,256]
    const float* adj = (const float*)d_in[1];   // [12,12]
    const float* W   = (const float*)d_in[2];   // [256,128]
    const float* a   = (const float*)d_in[3];   // [256,1]
    float* out       = (float*)d_out;           // [32768,12,128]

    wfrag_pre_kernel<<<128, 256>>>(W);

    const int smem_bytes =
        (HS_WORDS + 2 * D_OUT + N_NODE * N_NODE + BPC * 192) * 4;

    cudaFuncSetAttribute(gat_fused_kernel,
                         cudaFuncAttributeMaxDynamicSharedMemorySize, smem_bytes);

    gat_fused_kernel<<<B_TOT / BPC, 256, smem_bytes>>>(x, adj, a, out);
}

// round 13
// speedup vs baseline: 1.3509x; 1.1237x over previous
#include <cuda_runtime.h>
#include <cstdint>
#include <math.h>

// GAT layer, v8 (mma.sync; tcgen05 unavailable on this build's sm_103 target):
//   DENSE packing at 256 threads: BPC=8 -> 96 rows = 6 exact m16 tiles (no padding
//   work anywhere). Warp = (row-half g: 3 m-tiles, N-quarter nq: 32 cols),
//   acc[3][4][4] = 48 regs, 2 CTAs/SM.
//   B (W) fragments from L2-hot global WtF_g (coalesced LDG.128, no staging).
//   X staging double-buffered cp.async. Epilogue: H->smem (dense 96 rows),
//   float4-vectorized alpha loads, coalesced stores.

#define B_TOT   32768
#define N_NODE  12
#define F_IN    256
#define D_OUT   128
#define BPC     8
#define KC      64
#define BLK     132            // words per X fragment-block (128 used + 4 pad)
#define HST     132            // Hs row stride (words)

#define XBUF_WORDS (48 * BLK)              // 6336 per buffer (6 rowgroups x 8 ks)
#define HS_WORDS   (2 * XBUF_WORDS)        // 12672 = 96 rows * 132 (exact alias fit)

__device__ uint32_t WtF_g[4 * 64 * 32 * 4];   // [chunk][blk(ks,tp)][lane][v] tf32 bits

__device__ __forceinline__ uint32_t f2tf32(float f) {
    uint32_t r;
    asm("cvt.rna.tf32.f32 %0, %1;" : "=r"(r) : "f"(f));
    return r;
}

__device__ __forceinline__ void mma_tf32(float& c0, float& c1, float& c2, float& c3,
                                         uint32_t a0, uint32_t a1, uint32_t a2, uint32_t a3,
                                         uint32_t b0, uint32_t b1) {
    asm("mma.sync.aligned.m16n8k8.row.col.f32.tf32.tf32.f32 "
        "{%0,%1,%2,%3},{%4,%5,%6,%7},{%8,%9},{%0,%1,%2,%3};"
        : "+f"(c0), "+f"(c1), "+f"(c2), "+f"(c3)
        : "r"(a0), "r"(a1), "r"(a2), "r"(a3), "r"(b0), "r"(b1));
}

__device__ __forceinline__ uint32_t smem_u32(const void* p) {
    uint32_t a;
    asm("{ .reg .u64 t; cvta.to.shared.u64 t, %1; cvt.u32.u64 %0, t; }" : "=r"(a) : "l"(p));
    return a;
}

__device__ __forceinline__ void cp4(uint32_t dst, const void* src) {
    asm volatile("cp.async.ca.shared.global [%0], [%1], 4;" :: "r"(dst), "l"(src));
}
__device__ __forceinline__ void cp_commit() {
    asm volatile("cp.async.commit_group;");
}
__device__ __forceinline__ void cp_wait1() {
    asm volatile("cp.async.wait_group 1;" ::: "memory");
}
__device__ __forceinline__ void cp_wait0() {
    asm volatile("cp.async.wait_group 0;" ::: "memory");
}

__device__ __forceinline__ float elu_f(float v) {
    return v > 0.f ? v : expm1f(v);
}

// ---- pre-kernel: fragment-ordered tf32 W ----------------------------------
// word (ch, blk=(ks,tp), lane=(qq,mm), v=(tl,hi)) = tf32(W[k][n]),
//   k = 64ch + 8ks + mm + 4hi,  n = 16tp + 8tl + qq
__global__ void wfrag_pre_kernel(const float* __restrict__ W) {
    int idx = blockIdx.x * 256 + threadIdx.x;      // 0..32767
    int v   = idx & 3;
    int l   = (idx >> 2) & 31;
    int blk = (idx >> 7) & 63;
    int ch  = idx >> 13;
    int qq = l >> 2, mm = l & 3;
    int tl = v >> 1, hi = v & 1;
    int ks = blk >> 3, tp = blk & 7;
    int k = ch * 64 + ks * 8 + mm + 4 * hi;
    int n = 16 * tp + 8 * tl + qq;
    WtF_g[idx] = f2tf32(W[k * D_OUT + n]);
}

// stage X chunk c (dense rows; warp stages its own batch's 12 rows)
__device__ __forceinline__ void stage_x(uint32_t sbX, uint32_t bw, int c,
                                        const float* __restrict__ xw,
                                        int w, int lane) {
    #pragma unroll
    for (int it = 0; it < 6; it++) {
        int il  = it * 32 + lane;      // 0..191 = 12 rows x 16 float4
        int row = il >> 4;             // node 0..11
        int c4  = il & 15;
        const float* src = xw + row * F_IN + c * KC + 4 * c4;
        int r  = w * N_NODE + row;     // dense global row 0..95
        int g6 = r >> 4, qq = r & 7, rbit = (r >> 3) & 1;
        int ks = c4 >> 1, hi = c4 & 1;
        uint32_t dst = sbX + (bw + (g6 * 8 + ks) * BLK + qq * 16 + 2 * hi + rbit) * 4;
        #pragma unroll
        for (int s = 0; s < 4; s++) cp4(dst + s * 16, src + s);
    }
    cp_commit();
}

__global__ void __launch_bounds__(256, 2)
gat_fused_kernel(const float* __restrict__ x,    // [B, N, F]
                 const float* __restrict__ adj,  // [N, N]
                 const float* __restrict__ a,    // [2D, 1]
                 float* __restrict__ out)        // [B, N, D]
{
    extern __shared__ uint32_t smem[];
    uint32_t* XsF    = smem;                      // 2 buffers of XBUF_WORDS
    float*    Hs     = (float*)smem;              // aliases both buffers post-GEMM
    float*    sA     = (float*)(smem + HS_WORDS);
    float*    adjS   = sA + 2 * D_OUT;
    float*    alphaS = adjS + N_NODE * N_NODE;    // [8][144], row stride 12

    const uint32_t sbX = smem_u32(XsF);

    const int tid  = threadIdx.x;
    const int w    = tid >> 5;
    const int lane = tid & 31;
    const int g    = w >> 2;          // row half: m-tiles 3g..3g+2 (rows 48g..48g+47)
    const int nq   = w & 3;           // N quarter: cols 32nq..32nq+31
    const int b    = blockIdx.x * BPC + w;

    sA[tid] = a[tid];
    if (tid < N_NODE * N_NODE) adjS[tid] = adj[tid];

    float acc[3][4][4];
    #pragma unroll
    for (int u = 0; u < 3; u++)
        #pragma unroll
        for (int v = 0; v < 4; v++)
            acc[u][v][0] = acc[u][v][1] = acc[u][v][2] = acc[u][v][3] = 0.f;

    const float* xw = x + ((size_t)b * N_NODE) * F_IN;   // warp's batch

    // prologue: prefetch chunks 0 and 1
    stage_x(sbX, 0, 0, xw, w, lane);
    stage_x(sbX, XBUF_WORDS, 1, xw, w, lane);
    __syncthreads();   // also covers sA/adjS init

    #pragma unroll
    for (int c = 0; c < 4; c++) {
        const uint32_t bw = (c & 1) ? XBUF_WORDS : 0u;
        if (c < 3) cp_wait1(); else cp_wait0();
        __syncthreads();

        const uint32_t* Xp = XsF + bw + lane * 4;
        const uint4* __restrict__ Wg =
            (const uint4*)WtF_g + ((size_t)c * 64 + 2 * nq) * 32 + lane;

        #pragma unroll
        for (int ks = 0; ks < 8; ks++) {
            uint4 Bf0 = Wg[(ks * 8 + 0) * 32];
            uint4 Bf1 = Wg[(ks * 8 + 1) * 32];
            uint4 Af0 = *(const uint4*)(Xp + ((3 * g + 0) * 8 + ks) * BLK);
            uint4 Af1 = *(const uint4*)(Xp + ((3 * g + 1) * 8 + ks) * BLK);
            uint4 Af2 = *(const uint4*)(Xp + ((3 * g + 2) * 8 + ks) * BLK);

            mma_tf32(acc[0][0][0], acc[0][0][1], acc[0][0][2], acc[0][0][3],
                     Af0.x, Af0.y, Af0.z, Af0.w, Bf0.x, Bf0.y);
            mma_tf32(acc[0][1][0], acc[0][1][1], acc[0][1][2], acc[0][1][3],
                     Af0.x, Af0.y, Af0.z, Af0.w, Bf0.z, Bf0.w);
            mma_tf32(acc[0][2][0], acc[0][2][1], acc[0][2][2], acc[0][2][3],
                     Af0.x, Af0.y, Af0.z, Af0.w, Bf1.x, Bf1.y);
            mma_tf32(acc[0][3][0], acc[0][3][1], acc[0][3][2], acc[0][3][3],
                     Af0.x, Af0.y, Af0.z, Af0.w, Bf1.z, Bf1.w);

            mma_tf32(acc[1][0][0], acc[1][0][1], acc[1][0][2], acc[1][0][3],
                     Af1.x, Af1.y, Af1.z, Af1.w, Bf0.x, Bf0.y);
            mma_tf32(acc[1][1][0], acc[1][1][1], acc[1][1][2], acc[1][1][3],
                     Af1.x, Af1.y, Af1.z, Af1.w, Bf0.z, Bf0.w);
            mma_tf32(acc[1][2][0], acc[1][2][1], acc[1][2][2], acc[1][2][3],
                     Af1.x, Af1.y, Af1.z, Af1.w, Bf1.x, Bf1.y);
            mma_tf32(acc[1][3][0], acc[1][3][1], acc[1][3][2], acc[1][3][3],
                     Af1.x, Af1.y, Af1.z, Af1.w, Bf1.z, Bf1.w);

            mma_tf32(acc[2][0][0], acc[2][0][1], acc[2][0][2], acc[2][0][3],
                     Af2.x, Af2.y, Af2.z, Af2.w, Bf0.x, Bf0.y);
            mma_tf32(acc[2][1][0], acc[2][1][1], acc[2][1][2], acc[2][1][3],
                     Af2.x, Af2.y, Af2.z, Af2.w, Bf0.z, Bf0.w);
            mma_tf32(acc[2][2][0], acc[2][2][1], acc[2][2][2], acc[2][2][3],
                     Af2.x, Af2.y, Af2.z, Af2.w, Bf1.x, Bf1.y);
            mma_tf32(acc[2][3][0], acc[2][3][1], acc[2][3][2], acc[2][3][3],
                     Af2.x, Af2.y, Af2.z, Af2.w, Bf1.z, Bf1.w);
        }
        __syncthreads();
        if (c < 2) stage_x(sbX, bw, c + 2, xw, w, lane);
    }

    // ---- spill H (96 dense rows x 128) into Hs -----------------------------
    const int q = lane >> 2;
    const int m = lane & 3;
    #pragma unroll
    for (int u = 0; u < 3; u++) {
        const int row0 = (3 * g + u) * 16 + q;
        #pragma unroll
        for (int v = 0; v < 4; v++) {
            int col = 32 * nq + 8 * v + 2 * m;
            float* r0p = Hs + row0 * HST + col;
            *(float2*)r0p = make_float2(acc[u][v][0], acc[u][v][1]);
            *(float2*)(r0p + 8 * HST) = make_float2(acc[u][v][2], acc[u][v][3]);
        }
    }
    __syncthreads();

    // ---- dots + masked softmax (warp w owns batch w; lane = row i) ---------
    float sj = 0.f, si = 0.f;
    if (lane < N_NODE) {
        const float4* hr  = (const float4*)(Hs + (w * N_NODE + lane) * HST);
        const float4* ajp = (const float4*)sA;
        const float4* aip = (const float4*)(sA + D_OUT);
        #pragma unroll
        for (int cc = 0; cc < 32; cc++) {
            float4 hv = hr[cc];
            float4 av = ajp[cc], bv = aip[cc];
            sj += hv.x*av.x + hv.y*av.y + hv.z*av.z + hv.w*av.w;
            si += hv.x*bv.x + hv.y*bv.y + hv.z*bv.z + hv.w*bv.w;
        }
    }
    float sjv[N_NODE];
    #pragma unroll
    for (int j = 0; j < N_NODE; j++)
        sjv[j] = __shfl_sync(0xffffffffu, sj, j);

    if (lane < N_NODE) {
        float ev[N_NODE];
        float mx = -INFINITY;
        #pragma unroll
        for (int j = 0; j < N_NODE; j++) {
            float e = si + sjv[j];
            e = e > 0.f ? e : 0.2f * e;
            ev[j] = (adjS[lane * N_NODE + j] == 1.0f) ? e : -INFINITY;
            mx = fmaxf(mx, ev[j]);
        }
        float sum = 0.f;
        #pragma unroll
        for (int j = 0; j < N_NODE; j++) { ev[j] = __expf(ev[j] - mx); sum += ev[j]; }
        float inv = 1.f / sum;
        float* ap = alphaS + w * 144 + lane * 12;
        *(float4*)(ap)     = make_float4(ev[0]*inv, ev[1]*inv, ev[2]*inv,  ev[3]*inv);
        *(float4*)(ap + 4) = make_float4(ev[4]*inv, ev[5]*inv, ev[6]*inv,  ev[7]*inv);
        *(float4*)(ap + 8) = make_float4(ev[8]*inv, ev[9]*inv, ev[10]*inv, ev[11]*inv);
    }
    __syncwarp();

    // ---- h' = alpha @ H (float4 alpha loads), elu, store -------------------
    float4 o[N_NODE];
    #pragma unroll
    for (int i = 0; i < N_NODE; i++) o[i] = make_float4(0.f, 0.f, 0.f, 0.f);

    const float* hb  = Hs + (w * N_NODE) * HST + lane * 4;
    const float* alw = alphaS + w * 144;
    #pragma unroll
    for (int jb = 0; jb < 3; jb++) {
        float4 h0 = *(const float4*)(hb + (4 * jb + 0) * HST);
        float4 h1 = *(const float4*)(hb + (4 * jb + 1) * HST);
        float4 h2 = *(const float4*)(hb + (4 * jb + 2) * HST);
        float4 h3 = *(const float4*)(hb + (4 * jb + 3) * HST);
        #pragma unroll
        for (int i = 0; i < N_NODE; i++) {
            float4 av = *(const float4*)(alw + i * 12 + 4 * jb);
            o[i].x += av.x*h0.x + av.y*h1.x + av.z*h2.x + av.w*h3.x;
            o[i].y += av.x*h0.y + av.y*h1.y + av.z*h2.y + av.w*h3.y;
            o[i].z += av.x*h0.z + av.y*h1.z + av.z*h2.z + av.w*h3.z;
            o[i].w += av.x*h0.w + av.y*h1.w + av.z*h2.w + av.w*h3.w;
        }
    }
    #pragma unroll
    for (int i = 0; i < N_NODE; i++) {
        float4 r;
        r.x = elu_f(o[i].x);
        r.y = elu_f(o[i].y);
        r.z = elu_f(o[i].z);
        r.w = elu_f(o[i].w);
        *(float4*)(out + ((size_t)b * N_NODE + i) * D_OUT + lane * 4) = r;
    }
}

extern "C" void kernel_launch(void* const* d_in, const int* in_sizes, int n_in,
                              void* d_out, int out_size) {
    const float* x   = (const float*)d_in[0];   // [32768,12,256]
    const float* adj = (const float*)d_in[1];   // [12,12]
    const float* W   = (const float*)d_in[2];   // [256,128]
    const float* a   = (const float*)d_in[3];   // [256,1]
    float* out       = (float*)d_out;           // [32768,12,128]

    wfrag_pre_kernel<<<128, 256>>>(W);

    const int smem_bytes =
        (HS_WORDS + 2 * D_OUT + N_NODE * N_NODE + BPC * 144) * 4;

    cudaFuncSetAttribute(gat_fused_kernel,
                         cudaFuncAttributeMaxDynamicSharedMemorySize, smem_bytes);

    gat_fused_kernel<<<B_TOT / BPC, 256, smem_bytes>>>(x, adj, a, out);
}

// round 15
// speedup vs baseline: 1.5239x; 1.1281x over previous
#include <cuda_runtime.h>
#include <cstdint>
#include <math.h>

// GAT layer, v9 (resubmit — R14 was an infra failure, kernel never ran):
//   v8 dense packing (BPC=8 -> 96 rows = 6 m16 tiles, warp = row-half x N-quarter,
//   2 CTAs/SM) with ROW-MAJOR X smem (stride 68 words):
//   - staging = contiguous cp.async.16B (4x fewer LSU ops than swizzled 4B)
//   - A fragments = 4x LDS.32, banks (4*row + k) mod 32 -> conflict-free,
//     same wavefront count as LDS.128 from the swizzled layout.
//   B (W) fragments from L2-hot global WtF_g. Epilogue unchanged.

#define B_TOT   32768
#define N_NODE  12
#define F_IN    256
#define D_OUT   128
#define BPC     8
#define KC      64
#define XST     68             // X row stride in words: 68 % 32 == 4 -> conflict-free
#define HST     132            // Hs row stride (words)

#define XBUF_WORDS (96 * XST)              // 6528 per buffer
#define ALIAS_WORDS (2 * XBUF_WORDS)       // 13056 >= 96*132 = 12672 (Hs fits)

__device__ uint32_t WtF_g[4 * 64 * 32 * 4];   // [chunk][blk(ks,tp)][lane][v] tf32 bits

__device__ __forceinline__ uint32_t f2tf32(float f) {
    uint32_t r;
    asm("cvt.rna.tf32.f32 %0, %1;" : "=r"(r) : "f"(f));
    return r;
}

__device__ __forceinline__ void mma_tf32(float& c0, float& c1, float& c2, float& c3,
                                         uint32_t a0, uint32_t a1, uint32_t a2, uint32_t a3,
                                         uint32_t b0, uint32_t b1) {
    asm("mma.sync.aligned.m16n8k8.row.col.f32.tf32.tf32.f32 "
        "{%0,%1,%2,%3},{%4,%5,%6,%7},{%8,%9},{%0,%1,%2,%3};"
        : "+f"(c0), "+f"(c1), "+f"(c2), "+f"(c3)
        : "r"(a0), "r"(a1), "r"(a2), "r"(a3), "r"(b0), "r"(b1));
}

__device__ __forceinline__ uint32_t smem_u32(const void* p) {
    uint32_t a;
    asm("{ .reg .u64 t; cvta.to.shared.u64 t, %1; cvt.u32.u64 %0, t; }" : "=r"(a) : "l"(p));
    return a;
}

__device__ __forceinline__ void cp16(uint32_t dst, const void* src) {
    asm volatile("cp.async.ca.shared.global [%0], [%1], 16;" :: "r"(dst), "l"(src));
}
__device__ __forceinline__ void cp_commit() {
    asm volatile("cp.async.commit_group;");
}
__device__ __forceinline__ void cp_wait1() {
    asm volatile("cp.async.wait_group 1;" ::: "memory");
}
__device__ __forceinline__ void cp_wait0() {
    asm volatile("cp.async.wait_group 0;" ::: "memory");
}

__device__ __forceinline__ float elu_f(float v) {
    return v > 0.f ? v : expm1f(v);
}

// ---- pre-kernel: fragment-ordered tf32 W (unchanged layout) ----------------
// word (ch, blk=(ks,tp), lane=(qq,mm), v=(tl,hi)) = tf32(W[k][n]),
//   k = 64ch + 8ks + mm + 4hi,  n = 16tp + 8tl + qq
__global__ void wfrag_pre_kernel(const float* __restrict__ W) {
    int idx = blockIdx.x * 256 + threadIdx.x;      // 0..32767
    int v   = idx & 3;
    int l   = (idx >> 2) & 31;
    int blk = (idx >> 7) & 63;
    int ch  = idx >> 13;
    int qq = l >> 2, mm = l & 3;
    int tl = v >> 1, hi = v & 1;
    int ks = blk >> 3, tp = blk & 7;
    int k = ch * 64 + ks * 8 + mm + 4 * hi;
    int n = 16 * tp + 8 * tl + qq;
    WtF_g[idx] = f2tf32(W[k * D_OUT + n]);
}

// stage X chunk c: warp copies its own batch's 12 rows, contiguous 16B pieces
__device__ __forceinline__ void stage_x(uint32_t sbX, uint32_t bw, int c,
                                        const float* __restrict__ xw,
                                        int w, int lane) {
    #pragma unroll
    for (int it = 0; it < 6; it++) {
        int il  = it * 32 + lane;      // 0..191 = 12 rows x 16 float4
        int row = il >> 4;             // node 0..11
        int c4  = il & 15;
        const float* src = xw + row * F_IN + c * KC + 4 * c4;
        uint32_t dst = sbX + (bw + (w * N_NODE + row) * XST + 4 * c4) * 4;
        cp16(dst, src);
    }
    cp_commit();
}

__global__ void __launch_bounds__(256, 2)
gat_fused_kernel(const float* __restrict__ x,    // [B, N, F]
                 const float* __restrict__ adj,  // [N, N]
                 const float* __restrict__ a,    // [2D, 1]
                 float* __restrict__ out)        // [B, N, D]
{
    extern __shared__ uint32_t smem[];
    uint32_t* XsF    = smem;                      // 2 row-major buffers
    float*    Hs     = (float*)smem;              // aliases both buffers post-GEMM
    float*    sA     = (float*)(smem + ALIAS_WORDS);
    float*    adjS   = sA + 2 * D_OUT;
    float*    alphaS = adjS + N_NODE * N_NODE;    // [8][144], row stride 12

    const uint32_t sbX = smem_u32(XsF);

    const int tid  = threadIdx.x;
    const int w    = tid >> 5;
    const int lane = tid & 31;
    const int g    = w >> 2;          // row half: m-tiles 3g..3g+2
    const int nq   = w & 3;           // N quarter: cols 32nq..32nq+31
    const int qq   = lane >> 2;
    const int m    = lane & 3;
    const int b    = blockIdx.x * BPC + w;

    sA[tid] = a[tid];
    if (tid < N_NODE * N_NODE) adjS[tid] = adj[tid];

    float acc[3][4][4];
    #pragma unroll
    for (int u = 0; u < 3; u++)
        #pragma unroll
        for (int v = 0; v < 4; v++)
            acc[u][v][0] = acc[u][v][1] = acc[u][v][2] = acc[u][v][3] = 0.f;

    const float* xw = x + ((size_t)b * N_NODE) * F_IN;   // warp's batch

    // prologue: prefetch chunks 0 and 1
    stage_x(sbX, 0, 0, xw, w, lane);
    stage_x(sbX, XBUF_WORDS, 1, xw, w, lane);
    __syncthreads();   // also covers sA/adjS init

    #pragma unroll
    for (int c = 0; c < 4; c++) {
        const uint32_t bw = (c & 1) ? XBUF_WORDS : 0u;
        if (c < 3) cp_wait1(); else cp_wait0();
        __syncthreads();

        // per-warp A base: row (48g + qq), col m  (tile u adds 16 rows, ks adds 8 cols)
        const uint32_t* Xa = XsF + bw + (48 * g + qq) * XST + m;
        const uint4* __restrict__ Wg =
            (const uint4*)WtF_g + ((size_t)c * 64 + 2 * nq) * 32 + lane;

        #pragma unroll
        for (int ks = 0; ks < 8; ks++) {
            const int k0 = ks * 8;
            uint4 Bf0 = Wg[(ks * 8 + 0) * 32];
            uint4 Bf1 = Wg[(ks * 8 + 1) * 32];

            #pragma unroll
            for (int u = 0; u < 3; u++) {
                const uint32_t* Ap = Xa + u * 16 * XST + k0;
                uint32_t a0 = Ap[0];
                uint32_t a1 = Ap[8 * XST];
                uint32_t a2 = Ap[4];
                uint32_t a3 = Ap[8 * XST + 4];

                mma_tf32(acc[u][0][0], acc[u][0][1], acc[u][0][2], acc[u][0][3],
                         a0, a1, a2, a3, Bf0.x, Bf0.y);
                mma_tf32(acc[u][1][0], acc[u][1][1], acc[u][1][2], acc[u][1][3],
                         a0, a1, a2, a3, Bf0.z, Bf0.w);
                mma_tf32(acc[u][2][0], acc[u][2][1], acc[u][2][2], acc[u][2][3],
                         a0, a1, a2, a3, Bf1.x, Bf1.y);
                mma_tf32(acc[u][3][0], acc[u][3][1], acc[u][3][2], acc[u][3][3],
                         a0, a1, a2, a3, Bf1.z, Bf1.w);
            }
        }
        __syncthreads();
        if (c < 2) stage_x(sbX, bw, c + 2, xw, w, lane);
    }

    // ---- spill H (96 dense rows x 128) into Hs -----------------------------
    #pragma unroll
    for (int u = 0; u < 3; u++) {
        const int row0 = (3 * g + u) * 16 + qq;
        #pragma unroll
        for (int v = 0; v < 4; v++) {
            int col = 32 * nq + 8 * v + 2 * m;
            float* r0p = Hs + row0 * HST + col;
            *(float2*)r0p = make_float2(acc[u][v][0], acc[u][v][1]);
            *(float2*)(r0p + 8 * HST) = make_float2(acc[u][v][2], acc[u][v][3]);
        }
    }
    __syncthreads();

    // ---- dots + masked softmax (warp w owns batch w; lane = row i) ---------
    float sj = 0.f, si = 0.f;
    if (lane < N_NODE) {
        const float4* hr  = (const float4*)(Hs + (w * N_NODE + lane) * HST);
        const float4* ajp = (const float4*)sA;
        const float4* aip = (const float4*)(sA + D_OUT);
        #pragma unroll
        for (int cc = 0; cc < 32; cc++) {
            float4 hv = hr[cc];
            float4 av = ajp[cc], bv = aip[cc];
            sj += hv.x*av.x + hv.y*av.y + hv.z*av.z + hv.w*av.w;
            si += hv.x*bv.x + hv.y*bv.y + hv.z*bv.z + hv.w*bv.w;
        }
    }
    float sjv[N_NODE];
    #pragma unroll
    for (int j = 0; j < N_NODE; j++)
        sjv[j] = __shfl_sync(0xffffffffu, sj, j);

    if (lane < N_NODE) {
        float ev[N_NODE];
        float mx = -INFINITY;
        #pragma unroll
        for (int j = 0; j < N_NODE; j++) {
            float e = si + sjv[j];
            e = e > 0.f ? e : 0.2f * e;
            ev[j] = (adjS[lane * N_NODE + j] == 1.0f) ? e : -INFINITY;
            mx = fmaxf(mx, ev[j]);
        }
        float sum = 0.f;
        #pragma unroll
        for (int j = 0; j < N_NODE; j++) { ev[j] = __expf(ev[j] - mx); sum += ev[j]; }
        float inv = 1.f / sum;
        float* ap = alphaS + w * 144 + lane * 12;
        *(float4*)(ap)     = make_float4(ev[0]*inv, ev[1]*inv, ev[2]*inv,  ev[3]*inv);
        *(float4*)(ap + 4) = make_float4(ev[4]*inv, ev[5]*inv, ev[6]*inv,  ev[7]*inv);
        *(float4*)(ap + 8) = make_float4(ev[8]*inv, ev[9]*inv, ev[10]*inv, ev[11]*inv);
    }
    __syncwarp();

    // ---- h' = alpha @ H (float4 alpha loads), elu, store -------------------
    float4 o[N_NODE];
    #pragma unroll
    for (int i = 0; i < N_NODE; i++) o[i] = make_float4(0.f, 0.f, 0.f, 0.f);

    const float* hb  = Hs + (w * N_NODE) * HST + lane * 4;
    const float* alw = alphaS + w * 144;
    #pragma unroll
    for (int jb = 0; jb < 3; jb++) {
        float4 h0 = *(const float4*)(hb + (4 * jb + 0) * HST);
        float4 h1 = *(const float4*)(hb + (4 * jb + 1) * HST);
        float4 h2 = *(const float4*)(hb + (4 * jb + 2) * HST);
        float4 h3 = *(const float4*)(hb + (4 * jb + 3) * HST);
        #pragma unroll
        for (int i = 0; i < N_NODE; i++) {
            float4 av = *(const float4*)(alw + i * 12 + 4 * jb);
            o[i].x += av.x*h0.x + av.y*h1.x + av.z*h2.x + av.w*h3.x;
            o[i].y += av.x*h0.y + av.y*h1.y + av.z*h2.y + av.w*h3.y;
            o[i].z += av.x*h0.z + av.y*h1.z + av.z*h2.z + av.w*h3.z;
            o[i].w += av.x*h0.w + av.y*h1.w + av.z*h2.w + av.w*h3.w;
        }
    }
    #pragma unroll
    for (int i = 0; i < N_NODE; i++) {
        float4 r;
        r.x = elu_f(o[i].x);
        r.y = elu_f(o[i].y);
        r.z = elu_f(o[i].z);
        r.w = elu_f(o[i].w);
        *(float4*)(out + ((size_t)b * N_NODE + i) * D_OUT + lane * 4) = r;
    }
}

extern "C" void kernel_launch(void* const* d_in, const int* in_sizes, int n_in,
                              void* d_out, int out_size) {
    const float* x   = (const float*)d_in[0];   // [32768,12,256]
    const float* adj = (const float*)d_in[1];   // [12,12]
    const float* W   = (const float*)d_in[2];   // [256,128]
    const float* a   = (const float*)d_in[3];   // [256,1]
    float* out       = (float*)d_out;           // [32768,12,128]

    wfrag_pre_kernel<<<128, 256>>>(W);

    const int smem_bytes =
        (ALIAS_WORDS + 2 * D_OUT + N_NODE * N_NODE + BPC * 144) * 4;

    cudaFuncSetAttribute(gat_fused_kernel,
                         cudaFuncAttributeMaxDynamicSharedMemorySize, smem_bytes);

    gat_fused_kernel<<<B_TOT / BPC, 256, smem_bytes>>>(x, adj, a, out);
}